// round 8
// baseline (speedup 1.0000x reference)
#include <cuda_runtime.h>
#include <math.h>

#define NPTS  16384
#define R2    (1.0f / 256.0f)
#define NCELL 32768         // 8 clouds * 16^3, cell edge = r = 1/16
#define NBLK  1024
#define NTHR  256           // 16 lanes per point, 16 points per block
#define CAPB  16            // bucket slots per cell (lambda ~0.5)
#define CAPN  32            // per-point neighbor capacity (lambda ~2.1)
#define PPB   16            // points per block

// ---- scratch (static __device__; no allocation allowed) ----
__device__ int    g_cell_cnt[NCELL];          // zero-init; re-cleared each run
__device__ float4 g_bucket[NCELL * CAPB];     // x,y,z, idx-as-float
__device__ float  g_h0a[NPTS * 8];            // per-layer  x@W1x + b1
__device__ float  g_h0b[NPTS * 16];
__device__ float  g_h0c[NPTS * 32];

// ---- software grid barrier (all NBLK blocks co-resident by launch_bounds) ----
__device__ int          g_bar_count = 0;
__device__ volatile int g_bar_gen   = 0;

__device__ __forceinline__ void grid_barrier() {
    __syncthreads();
    if (threadIdx.x == 0) {
        __threadfence();
        const int gen = g_bar_gen;
        if (atomicAdd(&g_bar_count, 1) == NBLK - 1) {
            g_bar_count = 0;
            __threadfence();
            g_bar_gen = gen + 1;
        } else {
            while (g_bar_gen == gen) __nanosleep(32);
        }
        __threadfence();
    }
    __syncthreads();
}

__device__ __forceinline__ float celu1(float v) {
    return v > 0.0f ? v : expm1f(v);
}

// ---------------------------------------------------------------------------
// One persistent kernel, 3 grid barriers, 16 lanes per point:
//   P1 bucket-build + h0a + output copies | P2 query then layer a
//   | P3 layer b (1 ch/lane) | P4 layer c (2 ch/lane).
// Output tuple layout: out = [pos(3N) | feat(32N) | batch(N)].
// ---------------------------------------------------------------------------
__global__ __launch_bounds__(NTHR, 7) void fused_kernel(
    const float* __restrict__ pos, const int* __restrict__ batch,
    const float* __restrict__ W1a, const float* __restrict__ b1a,
    const float* __restrict__ W2a, const float* __restrict__ b2a,
    const float* __restrict__ W1b, const float* __restrict__ b1b,
    const float* __restrict__ W2b, const float* __restrict__ b2b,
    const float* __restrict__ W1c, const float* __restrict__ b1c,
    const float* __restrict__ W2c, const float* __restrict__ b2c,
    float* __restrict__ out)
{
    // weights in smem (broadcast LDS; inner-loop weights hoisted to regs below)
    __shared__ float sWar[24],  sW2a[64],   sB2a[8],  sWbx[128], sB1b[16];
    __shared__ float sWbr[48],  sW2b[256],  sB2b[16], sWcx[512], sB1c[32];
    __shared__ float sWcr[96],  sW2c[1024], sB2c[32];
    __shared__ int    s_cnt[PPB];
    __shared__ int    s_nidx[PPB * CAPN];
    __shared__ float4 s_nrel[PPB * CAPN];

    const int tid = threadIdx.x;
    const int blk = blockIdx.x;
    const int gtid = blk * NTHR + tid;
    const int r = tid & 15;       // lane within point-group (0..15)
    const int p = tid >> 4;       // point within block (0..15)
    const int i = blk * PPB + p;  // global point id

    for (int k = tid; k < 24;   k += NTHR) sWar[k] = W1a[24 + k];        // rel rows
    for (int k = tid; k < 64;   k += NTHR) sW2a[k] = W2a[k];
    for (int k = tid; k < 8;    k += NTHR) sB2a[k] = b2a[k];
    for (int k = tid; k < 128;  k += NTHR) sWbx[k] = W1b[k];             // x rows
    for (int k = tid; k < 16;   k += NTHR) sB1b[k] = b1b[k];
    for (int k = tid; k < 48;   k += NTHR) sWbr[k] = W1b[128 + k];       // rel rows
    for (int k = tid; k < 256;  k += NTHR) sW2b[k] = W2b[k];
    for (int k = tid; k < 16;   k += NTHR) sB2b[k] = b2b[k];
    for (int k = tid; k < 512;  k += NTHR) sWcx[k] = W1c[k];             // x rows
    for (int k = tid; k < 32;   k += NTHR) sB1c[k] = b1c[k];
    for (int k = tid; k < 96;   k += NTHR) sWcr[k] = W1c[512 + k];       // rel rows
    for (int k = tid; k < 1024; k += NTHR) sW2c[k] = W2c[k];
    for (int k = tid; k < 32;   k += NTHR) sB2c[k] = b2c[k];

    // ---- P1: bucket insert + h0a (lanes 0-7) + output pos/batch copies ----
    const float px = pos[3 * i + 0];
    const float py = pos[3 * i + 1];
    const float pz = pos[3 * i + 2];
    const float si = fmaf(pz, pz, fmaf(py, py, px * px));
    const int bb = batch[i];
    const int cx0 = min(15, max(0, (int)(px * 16.0f)));
    const int cy0 = min(15, max(0, (int)(py * 16.0f)));
    const int cz0 = min(15, max(0, (int)(pz * 16.0f)));
    const int c = (bb << 12) | (cz0 << 8) | (cy0 << 4) | cx0;

    if (r == 8) {
        out[3 * i + 0] = px;
        out[3 * i + 1] = py;
        out[3 * i + 2] = pz;
        out[(size_t)NPTS * 35 + i] = (float)bb;
    } else if (r == 9) {
        const int slot = atomicAdd(&g_cell_cnt[c], 1);
        if (slot < CAPB)
            g_bucket[c * CAPB + slot] = make_float4(px, py, pz, __int_as_float(i));
    } else if (r < 8) {
        // h0a channel r = pos @ W1a[0:3][:,r] + b1a[r]
        float s = b1a[r];
        s = fmaf(px, W1a[0 * 8 + r], s);
        s = fmaf(py, W1a[1 * 8 + r], s);
        s = fmaf(pz, W1a[2 * 8 + r], s);
        g_h0a[i * 8 + r] = s;
    }
    grid_barrier();

    // ---- P2: radius query (pass 1: record only) + layer a ----
    int cnt;
    {
        if (r == 0) s_cnt[p] = 0;
        __syncwarp();

        const int cb = c & 0xF000;

        // this lane's <=2 stencil cells; prefetch counts
        int cells[2], cnts[2];
#pragma unroll
        for (int t = 0; t < 2; ++t) {
            const int k = r + 16 * t;
            bool ok = (k < 27);
            const int z = cz0 + k / 9 - 1;
            const int y = cy0 + (k / 3) % 3 - 1;
            const int x = cx0 + k % 3 - 1;
            ok = ok && ((unsigned)(z | y | x) <= 15u);
            cells[t] = ok ? (cb | (z << 8) | (y << 4) | x) : 0;
            cnts[t]  = ok ? min(g_cell_cnt[cells[t]], CAPB) : 0;
        }

        // pass 1: d^2 test + record (accept branch is tiny)
#pragma unroll
        for (int t = 0; t < 2; ++t) {
            const int base = cells[t] * CAPB;
            for (int e = 0; e < cnts[t]; ++e) {
                const float4 q = g_bucket[base + e];
                const float sj  = fmaf(q.z, q.z, fmaf(q.y, q.y, q.x * q.x));
                const float dot = px * q.x + py * q.y + pz * q.z;
                const float d2  = si + sj - 2.0f * dot;   // reference's formula
                if (d2 <= R2) {
                    const int slot = atomicAdd(&s_cnt[p], 1);
                    if (slot < CAPN) {
                        s_nidx[p * CAPN + slot] = __float_as_int(q.w);
                        s_nrel[p * CAPN + slot] =
                            make_float4(q.x - px, q.y - py, q.z - pz, 0.0f);
                    }
                }
            }
        }
        __syncwarp();
        cnt = min(s_cnt[p], CAPN);

        // pass 2: channel m = r&7, neighbors split 2-way by r>>3
        const int m = r & 7;
        const float wa0 = sWar[0 * 8 + m];
        const float wa1 = sWar[1 * 8 + m];
        const float wa2 = sWar[2 * 8 + m];
        float acc = -INFINITY;
        for (int n = (r >> 3); n < cnt; n += 2) {
            const float4 rel = s_nrel[p * CAPN + n];
            const int j = s_nidx[p * CAPN + n];
            float h = g_h0a[j * 8 + m];              // coalesced 4B/lane
            h = fmaf(rel.x, wa0, h);
            h = fmaf(rel.y, wa1, h);
            h = fmaf(rel.z, wa2, h);
            acc = fmaxf(acc, fmaxf(h, 0.0f));
        }
        __syncwarp();
        // combine neighbor halves: lanes m and m+8 both end with full channel-m max
        acc = fmaxf(acc, __shfl_xor_sync(0xffffffffu, acc, 8, 16));

        // epilogue: v[r&7] = celu(acc_full @ W2a + b2a); channel q lives in lane q
        float v = sB2a[m];
#pragma unroll
        for (int q8 = 0; q8 < 8; ++q8) {
            const float aq = __shfl_sync(0xffffffffu, acc, q8, 16);  // channel q8
            v = fmaf(aq, sW2a[q8 * 8 + m], v);
        }
        v = celu1(v);

        // h0b channel r = b1b[r] + v_full @ W1b[0:8][:,r]; v[o] from lane o
        float h0 = sB1b[r];
#pragma unroll
        for (int o = 0; o < 8; ++o) {
            const float vo = __shfl_sync(0xffffffffu, v, o, 16);
            h0 = fmaf(vo, sWbx[o * 16 + r], h0);
        }
        g_h0b[(size_t)i * 16 + r] = h0;              // 16 lanes x 4B = 64B coalesced
    }
    grid_barrier();

    // ---- P3: layer b (lane owns channel r) ----
    {
        if (gtid < NCELL) g_cell_cnt[gtid] = 0;   // reset for next graph replay

        const float wb0 = sWbr[0 * 16 + r];
        const float wb1 = sWbr[1 * 16 + r];
        const float wb2 = sWbr[2 * 16 + r];

        float a = -INFINITY;
        for (int n = 0; n < cnt; ++n) {
            const float4 rel = s_nrel[p * CAPN + n];
            const int j = s_nidx[p * CAPN + n];
            float h = g_h0b[(size_t)j * 16 + r];     // coalesced 4B/lane
            h = fmaf(rel.x, wb0, h);
            h = fmaf(rel.y, wb1, h);
            h = fmaf(rel.z, wb2, h);
            a = fmaxf(a, fmaxf(h, 0.0f));
        }
        __syncwarp();

        // v[r] = celu(acc_full @ W2b + b2b), acc channel mm from lane mm
        float v = sB2b[r];
#pragma unroll
        for (int mm = 0; mm < 16; ++mm) {
            const float am = __shfl_sync(0xffffffffu, a, mm, 16);
            v = fmaf(am, sW2b[mm * 16 + r], v);
        }
        v = celu1(v);

        // h0c channels 2r, 2r+1 = b1c + v_full @ W1c[0:16]
        float c0 = sB1c[2 * r + 0], c1 = sB1c[2 * r + 1];
#pragma unroll
        for (int oo = 0; oo < 16; ++oo) {
            const float vo = __shfl_sync(0xffffffffu, v, oo, 16);
            c0 = fmaf(vo, sWcx[oo * 32 + 2 * r + 0], c0);
            c1 = fmaf(vo, sWcx[oo * 32 + 2 * r + 1], c1);
        }
        *(float2*)&g_h0c[(size_t)i * 32 + 2 * r] = make_float2(c0, c1);
    }
    grid_barrier();

    // ---- P4: layer c (lane owns channels 2r, 2r+1) ----
    {
        const float wc00 = sWcr[0 * 32 + 2 * r], wc01 = sWcr[0 * 32 + 2 * r + 1];
        const float wc10 = sWcr[1 * 32 + 2 * r], wc11 = sWcr[1 * 32 + 2 * r + 1];
        const float wc20 = sWcr[2 * 32 + 2 * r], wc21 = sWcr[2 * 32 + 2 * r + 1];

        float a0 = -INFINITY, a1 = -INFINITY;
        for (int n = 0; n < cnt; ++n) {
            const float4 rel = s_nrel[p * CAPN + n];
            const int j = s_nidx[p * CAPN + n];
            const float2 hc = *(const float2*)&g_h0c[(size_t)j * 32 + 2 * r];
            float h = hc.x;
            h = fmaf(rel.x, wc00, h);
            h = fmaf(rel.y, wc10, h);
            h = fmaf(rel.z, wc20, h);
            a0 = fmaxf(a0, fmaxf(h, 0.0f));
            h = hc.y;
            h = fmaf(rel.x, wc01, h);
            h = fmaf(rel.y, wc11, h);
            h = fmaf(rel.z, wc21, h);
            a1 = fmaxf(a1, fmaxf(h, 0.0f));
        }
        __syncwarp();

        // s[2r], s[2r+1] = celu(acc_full @ W2c + b2c); channels 2mm,2mm+1 in lane mm
        float s0 = sB2c[2 * r + 0], s1 = sB2c[2 * r + 1];
#pragma unroll
        for (int mm = 0; mm < 16; ++mm) {
            const float am0 = __shfl_sync(0xffffffffu, a0, mm, 16);  // ch 2mm
            const float am1 = __shfl_sync(0xffffffffu, a1, mm, 16);  // ch 2mm+1
            s0 = fmaf(am0, sW2c[(2 * mm + 0) * 32 + 2 * r + 0], s0);
            s0 = fmaf(am1, sW2c[(2 * mm + 1) * 32 + 2 * r + 0], s0);
            s1 = fmaf(am0, sW2c[(2 * mm + 0) * 32 + 2 * r + 1], s1);
            s1 = fmaf(am1, sW2c[(2 * mm + 1) * 32 + 2 * r + 1], s1);
        }
        float2* dst = (float2*)(out + (size_t)NPTS * 3 + (size_t)i * 32 + 2 * r);
        *dst = make_float2(celu1(s0), celu1(s1));
    }
}

// ---------------------------------------------------------------------------
// Launch. Inputs: 0 pos | 1 rgb (unused) | 2 batch |
//  3 W1a[6,8] 4 b1a 5 W2a 6 b2a | 7 W1b[11,16] 8 b1b 9 W2b 10 b2b
// 11 W1c[19,32] 12 b1c 13 W2c 14 b2c
// Output: [pos(3N) | feat(32N) | batch(N)] float32.
// ---------------------------------------------------------------------------
extern "C" void kernel_launch(void* const* d_in, const int* in_sizes, int n_in,
                              void* d_out, int out_size)
{
    fused_kernel<<<NBLK, NTHR>>>(
        (const float*)d_in[0], (const int*)d_in[2],
        (const float*)d_in[3],  (const float*)d_in[4],
        (const float*)d_in[5],  (const float*)d_in[6],
        (const float*)d_in[7],  (const float*)d_in[8],
        (const float*)d_in[9],  (const float*)d_in[10],
        (const float*)d_in[11], (const float*)d_in[12],
        (const float*)d_in[13], (const float*)d_in[14],
        (float*)d_out);
}